// round 13
// baseline (speedup 1.0000x reference)
#include <cuda_runtime.h>
#include <math_constants.h>

// SpatialAttention: out = x * hardsigmoid(conv3x3([mean_c(x); max_c(x)]))
// x: [16, 256, 128, 128] fp32, conv_w: [1, 2, 3, 3] fp32.
//
// Two-stream pipeline + R2-proven reduce shape:
//   reduce: thread = (seg, col); 8 segs x 32 channels; 512B warp segments;
//           32-deep unrolled loop; partials straight to gmem (NO smem fold,
//           no __syncthreads tail). R2 measured ~4.3 TB/s with this shape;
//           every smem-fold variant since capped at 2.2-2.5 TB/s.
//   conv:   folds the 8 partials into smem (4 rows + halo), then 3x3 taps.
//   mul:    x via __ldcs (L2 hit, last use), out via __stcs.

#define BATCH 16
#define CH    256
#define HH    128
#define WW    128
#define HWSZ  (HH * WW)          // 16384
#define HW4   (HWSZ / 4)         // 4096 float4 cols per (b,c) plane
#define NCHNK 16                 // 1 batch per chunk (16 MiB x-slice)

#define SEG   8                  // channel segments
#define CPS   (CH / SEG)         // 32 channels per segment

#define R_BLK (SEG * HW4 / 256)  // 128 reduce blocks per chunk
#define C_BLK 64                 // conv blocks per chunk (256 pos each)
#define M_BLK 4096               // mul blocks per chunk

__device__ float g_pavg[SEG][BATCH * HWSZ];   // per-seg partial sums
__device__ float g_pmax[SEG][BATCH * HWSZ];   // per-seg partial maxes
__device__ float g_att[BATCH * HWSZ];

// ---------------------------------------------------------------------------
// reduce: one thread per (seg, float4-col). 32 channels, unroll 8, no sync.
// ---------------------------------------------------------------------------
__global__ void __launch_bounds__(256) reduce_kernel(const float* __restrict__ x, int b) {
    int tid = blockIdx.x * 256 + threadIdx.x;   // 0 .. SEG*HW4-1
    int col = tid & (HW4 - 1);
    int seg = tid >> 12;                        // 0..7

    const float4* xp = reinterpret_cast<const float4*>(x)
                     + (size_t)b * CH * HW4 + (size_t)seg * CPS * HW4 + col;

    float4 s = make_float4(0.f, 0.f, 0.f, 0.f);
    float4 m = make_float4(-CUDART_INF_F, -CUDART_INF_F, -CUDART_INF_F, -CUDART_INF_F);

    #pragma unroll 8
    for (int c = 0; c < CPS; c++) {
        float4 v = xp[c * HW4];
        s.x += v.x; s.y += v.y; s.z += v.z; s.w += v.w;
        m.x = fmaxf(m.x, v.x); m.y = fmaxf(m.y, v.y);
        m.z = fmaxf(m.z, v.z); m.w = fmaxf(m.w, v.w);
    }

    reinterpret_cast<float4*>(g_pavg[seg])[b * HW4 + col] = s;
    reinterpret_cast<float4*>(g_pmax[seg])[b * HW4 + col] = m;
}

// ---------------------------------------------------------------------------
// conv: block covers 2 rows (256 positions). Fold 8 partials into smem for
// the 4 rows needed (2 + halo), then 3x3 conv + hardsigmoid from smem.
// ---------------------------------------------------------------------------
__global__ void __launch_bounds__(256) conv_kernel(const float* __restrict__ wt, int b) {
    __shared__ float sA[4 * WW];
    __shared__ float sM[4 * WW];

    int bk   = blockIdx.x;            // 0..63, rows 2bk..2bk+1
    int row0 = 2 * bk - 1;            // smem row 0 = global row row0
    int t    = threadIdx.x;

    const float inv = 1.0f / (float)CH;

    // Fold partials for 4 rows (512 positions): 2 positions per thread.
    #pragma unroll
    for (int j = t; j < 4 * WW; j += 256) {
        int gh = row0 + (j >> 7);     // global row
        float av = 0.f, mx = -CUDART_INF_F;
        if (gh >= 0 && gh < HH) {
            int o = b * HWSZ + gh * WW + (j & (WW - 1));
            #pragma unroll
            for (int sgi = 0; sgi < SEG; sgi++) {
                av += __ldg(&g_pavg[sgi][o]);
                mx  = fmaxf(mx, __ldg(&g_pmax[sgi][o]));
            }
            av *= inv;
        }
        sA[j] = av; sM[j] = mx;
    }
    __syncthreads();

    int h  = 2 * bk + (t >> 7);       // global row of this thread
    int w  = t & (WW - 1);
    int lr = (t >> 7) + 1;            // local smem row (1 or 2)

    float acc = 0.f;
    #pragma unroll
    for (int kh = 0; kh < 3; kh++) {
        int hh = h + kh - 1;
        if (hh < 0 || hh >= HH) continue;
        int lrow = lr + kh - 1;       // 0..3
        #pragma unroll
        for (int kw = 0; kw < 3; kw++) {
            int ww = w + kw - 1;
            if (ww < 0 || ww >= WW) continue;
            int o = lrow * WW + ww;
            acc += __ldg(&wt[kh * 3 + kw])     * sA[o]
                 + __ldg(&wt[9 + kh * 3 + kw]) * sM[o];
        }
    }
    float y = fminf(fmaxf(acc + 3.0f, 0.0f), 6.0f) * (1.0f / 6.0f);
    g_att[b * HWSZ + h * WW + w] = y;
}

// ---------------------------------------------------------------------------
__global__ void __launch_bounds__(256) mul_kernel(const float* __restrict__ x,
                                                  float* __restrict__ out, int b) {
    int idx = blockIdx.x * 256 + threadIdx.x;   // 0 .. CH*HW4-1
    int col = idx & (HW4 - 1);

    size_t gidx = (size_t)b * CH * HW4 + idx;

    float4 v = __ldcs(reinterpret_cast<const float4*>(x) + gidx);
    float4 a = __ldg(reinterpret_cast<const float4*>(g_att) + (size_t)b * HW4 + col);

    v.x *= a.x; v.y *= a.y; v.z *= a.z; v.w *= a.w;
    __stcs(reinterpret_cast<float4*>(out) + gidx, v);
}

// ---------------------------------------------------------------------------
extern "C" void kernel_launch(void* const* d_in, const int* in_sizes, int n_in,
                              void* d_out, int out_size) {
    const float* x  = (const float*)d_in[0];
    const float* wt = (const float*)d_in[1];
    float* out      = (float*)d_out;

    static cudaStream_t sB = []() {
        cudaStream_t s;
        cudaStreamCreateWithFlags(&s, cudaStreamNonBlocking);
        return s;
    }();
    static cudaEvent_t evFork = []() {
        cudaEvent_t e;
        cudaEventCreateWithFlags(&e, cudaEventDisableTiming);
        return e;
    }();
    static cudaEvent_t evJoin = []() {
        cudaEvent_t e;
        cudaEventCreateWithFlags(&e, cudaEventDisableTiming);
        return e;
    }();

    // Fork second stream into the captured graph.
    cudaEventRecord(evFork, 0);
    cudaStreamWaitEvent(sB, evFork, 0);

    // Even chunks on capture stream, odd chunks on sB.
    for (int b = 0; b < NCHNK; b++) {
        cudaStream_t s = (b & 1) ? sB : (cudaStream_t)0;
        reduce_kernel<<<R_BLK, 256, 0, s>>>(x, b);
        conv_kernel<<<C_BLK, 256, 0, s>>>(wt, b);
        mul_kernel<<<M_BLK, 256, 0, s>>>(x, out, b);
    }

    // Join.
    cudaEventRecord(evJoin, sB);
    cudaStreamWaitEvent(0, evJoin, 0);
}